// round 4
// baseline (speedup 1.0000x reference)
#include <cuda_runtime.h>

// BoxFilter: out[b,c,i,j] = 9x9 zero-padded window sum of x.
// Fixed shape (8,3,1080,1920) fp32, r=4.
//
// v3: ring buffer moved to SMEM (frees ~36 regs), STRIP 108->60 (grid 450->810
// blocks so 4-5 blocks/SM can co-reside), register prefetch depth 2 to double
// per-warp MLP, streaming stores. Goal: saturate DRAM (was 58% busy).

#define RR 4
#define WD 1920
#define HD 1080
#define NIMG 24                 // B*C
#define TILE_W 128              // 32 lanes x float4
#define NTX (WD / TILE_W)       // 15
#define STRIP 60                // output rows per warp
#define NSTR (HD / STRIP)       // 18
#define TOTAL_WARPS (NIMG * NTX * NSTR)   // 6480
#define WPB 8
#define THREADS (WPB * 32)
#define NBLOCKS (TOTAL_WARPS / WPB)       // 810
#define RING 9

__device__ __forceinline__ float4 f4zero() { return make_float4(0.f, 0.f, 0.f, 0.f); }

__device__ __forceinline__ float4 shfl_up_f4(float4 v) {
    float4 r;
    r.x = __shfl_up_sync(0xffffffffu, v.x, 1);
    r.y = __shfl_up_sync(0xffffffffu, v.y, 1);
    r.z = __shfl_up_sync(0xffffffffu, v.z, 1);
    r.w = __shfl_up_sync(0xffffffffu, v.w, 1);
    return r;
}
__device__ __forceinline__ float4 shfl_dn_f4(float4 v) {
    float4 r;
    r.x = __shfl_down_sync(0xffffffffu, v.x, 1);
    r.y = __shfl_down_sync(0xffffffffu, v.y, 1);
    r.z = __shfl_down_sync(0xffffffffu, v.z, 1);
    r.w = __shfl_down_sync(0xffffffffu, v.w, 1);
    return r;
}
__device__ __forceinline__ float4 add4(float4 a, float4 b) {
    return make_float4(a.x + b.x, a.y + b.y, a.z + b.z, a.w + b.w);
}
__device__ __forceinline__ float4 sub4(float4 a, float4 b) {
    return make_float4(a.x - b.x, a.y - b.y, a.z - b.z, a.w - b.w);
}

struct Raw {
    float4 v;    // this lane's 4 columns
    float4 ext;  // lane 0: cols col-4..col-1 ; lane 31: cols col+4..col+7
};

__global__ __launch_bounds__(THREADS)
void boxfilter9x9_kernel(const float* __restrict__ x, float* __restrict__ out) {
    __shared__ float4 ring_sm[WPB][RING][32];

    const int warp = threadIdx.x >> 5;
    const int lane = threadIdx.x & 31;
    const int gwarp = blockIdx.x * WPB + warp;

    const int strip = gwarp % NSTR;
    const int t     = gwarp / NSTR;
    const int tx    = t % NTX;
    const int img   = t / NTX;

    const float* __restrict__ base  = x   + (size_t)img * HD * WD;
    float* __restrict__       obase = out + (size_t)img * HD * WD;

    const int col  = tx * TILE_W + lane * 4;
    const int row0 = strip * STRIP;

    const bool need_left  = (lane == 0);
    const bool need_right = (lane == 31);
    const bool left_edge  = (col == 0);
    const bool right_edge = (col + 4 >= WD);

    float4* const myring = &ring_sm[warp][0][lane];  // slot stride = 32 float4s

    // ---- raw row load: 1 LDG.128/lane (+1 halo LDG.128 on lanes 0/31) ----
    auto rawload = [&](int ir) -> Raw {
        Raw r;
        if ((unsigned)ir >= (unsigned)HD) { r.v = f4zero(); r.ext = f4zero(); return r; }
        const float* rp = base + (size_t)ir * WD;
        r.v = *reinterpret_cast<const float4*>(rp + col);
        r.ext = f4zero();
        if (need_left && !left_edge)
            r.ext = *reinterpret_cast<const float4*>(rp + col - 4);
        if (need_right && !right_edge)
            r.ext = *reinterpret_cast<const float4*>(rp + col + 4);
        return r;
    };

    // ---- horizontal 9-tap sums for this lane's 4 columns ----
    auto hcompute = [&](Raw r) -> float4 {
        float4 p = shfl_up_f4(r.v);
        float4 n = shfl_dn_f4(r.v);
        if (need_left)  p = r.ext;
        if (need_right) n = r.ext;
        const float a0 = p.x, a1 = p.y, a2 = p.z, a3 = p.w;
        const float a4 = r.v.x, a5 = r.v.y, a6 = r.v.z, a7 = r.v.w;
        const float a8 = n.x, a9 = n.y, a10 = n.z, a11 = n.w;
        float h0 = ((((((((a0 + a1) + a2) + a3) + a4) + a5) + a6) + a7) + a8);
        float h1 = h0 - a0 + a9;
        float h2 = h1 - a1 + a10;
        float h3 = h2 - a2 + a11;
        return make_float4(h0, h1, h2, h3);
    };

    // ---- prologue: fill ring slots 0..7 with h(row0-4 .. row0+3) ----
    // Batched in groups of 4 so ptxas front-batches the LDGs (MLP=4).
    float4 vsum = f4zero();
    {
        Raw pr[4];
#pragma unroll
        for (int k = 0; k < 4; ++k) pr[k] = rawload(row0 - RR + k);
#pragma unroll
        for (int k = 0; k < 4; ++k) {
            float4 h = hcompute(pr[k]);
            myring[k * 32] = h;
            vsum = add4(vsum, h);
        }
#pragma unroll
        for (int k = 0; k < 4; ++k) pr[k] = rawload(row0 + k);
#pragma unroll
        for (int k = 0; k < 4; ++k) {
            float4 h = hcompute(pr[k]);
            myring[(4 + k) * 32] = h;
            vsum = add4(vsum, h);
        }
    }

    // ---- main loop: prefetch depth 2 ----
    Raw q0 = rawload(row0 + RR);
    Raw q1 = rawload(row0 + RR + 1);

    int s_new = 8;   // slot for h(i+4)
    int s_old = 0;   // slot of h(i-4)

#pragma unroll 3
    for (int i = row0; i < row0 + STRIP; ++i) {
        Raw cur = q0;
        q0 = q1;
        q1 = rawload(i + RR + 2);            // keep 2 rows in flight

        float4 old = myring[s_old * 32];     // h(i-4), written 9 iters ago
        float4 h   = hcompute(cur);          // h(i+4)
        myring[s_new * 32] = h;

        vsum = add4(vsum, h);
        __stcs(reinterpret_cast<float4*>(obase + (size_t)i * WD + col), vsum);
        vsum = sub4(vsum, old);

        s_new = (s_new + 1 == RING) ? 0 : s_new + 1;
        s_old = (s_old + 1 == RING) ? 0 : s_old + 1;
    }
}

extern "C" void kernel_launch(void* const* d_in, const int* in_sizes, int n_in,
                              void* d_out, int out_size) {
    const float* x = (const float*)d_in[0];
    // d_in[1] is r (int32, fixed at 4) — hardcoded.
    float* out = (float*)d_out;
    boxfilter9x9_kernel<<<NBLOCKS, THREADS>>>(x, out);
}

// round 8
// speedup vs baseline: 1.0011x; 1.0011x over previous
#include <cuda_runtime.h>

// BoxFilter 9x9 zero-padded window sum. Fixed shape (8,3,1080,1920) fp32, r=4.
//
// v5 = v4 with the right-halo guard fixed (col <= WD-8, was WD-12, which
// zeroed a real halo for the col=1912 lane -> rel_err 2.4e-2).
//
// Design: single-wave residency. 1080 blocks x 128 thr, <=64 regs -> 8
// blocks/SM -> ALL blocks resident at t=0 (no wave-quantization tail).
// Horizontal window via 3 aligned LDG.128 (p/v/n); overlap lines hit L1/L2.
// Vertical 9-row running sum in a register ring.

#define RR 4
#define WD 1920
#define HD 1080
#define NIMG 24                  // B*C
#define TILE_W 128               // 32 lanes x float4
#define NTX (WD / TILE_W)        // 15
#define STRIP 90                 // output rows per warp
#define NSTR (HD / STRIP)        // 12
#define WPB 4
#define THREADS (WPB * 32)       // 128
#define NBLOCKS (NIMG * NTX * NSTR / WPB)   // 4320/4 = 1080
#define RING 9

__device__ __forceinline__ float4 f4zero() { return make_float4(0.f, 0.f, 0.f, 0.f); }
__device__ __forceinline__ float4 add4(float4 a, float4 b) {
    return make_float4(a.x + b.x, a.y + b.y, a.z + b.z, a.w + b.w);
}
__device__ __forceinline__ float4 sub4(float4 a, float4 b) {
    return make_float4(a.x - b.x, a.y - b.y, a.z - b.z, a.w - b.w);
}

__global__ __launch_bounds__(THREADS, 8)
void boxfilter9x9_kernel(const float* __restrict__ x, float* __restrict__ out) {
    const int lane  = threadIdx.x & 31;
    const int gwarp = blockIdx.x * WPB + (threadIdx.x >> 5);

    const int strip = gwarp % NSTR;
    const int t     = gwarp / NSTR;
    const int tx    = t % NTX;
    const int img   = t / NTX;

    const float* __restrict__ base  = x   + (size_t)img * HD * WD;
    float* __restrict__       obase = out + (size_t)img * HD * WD;

    const int col  = tx * TILE_W + lane * 4;
    const int row0 = strip * STRIP;

    const bool has_l = (col >= 4);         // p covers col-4..col-1
    const bool has_r = (col <= WD - 8);    // n covers col+4..col+7 (in-range iff col<=1912)

    // Prefetched center load for one row (4 regs).
    auto vload = [&](int ir) -> float4 {
        if ((unsigned)ir >= (unsigned)HD) return f4zero();
        return *reinterpret_cast<const float4*>(base + (size_t)ir * WD + col);
    };

    // Horizontal 9-tap sums for 4 columns. p/n loaded just-in-time (L1/L2 hits:
    // same lines as neighboring lanes' v loads). Tree adds, short dep chain.
    auto hsum = [&](int ir, float4 v) -> float4 {
        float4 p = f4zero(), n = f4zero();
        if ((unsigned)ir < (unsigned)HD) {
            const float* rp = base + (size_t)ir * WD;
            if (has_l) p = *reinterpret_cast<const float4*>(rp + col - 4);
            if (has_r) n = *reinterpret_cast<const float4*>(rp + col + 4);
        }
        const float a0 = p.x, a1 = p.y, a2 = p.z, a3 = p.w;
        const float a4 = v.x, a5 = v.y, a6 = v.z, a7 = v.w;
        const float a8 = n.x, a9 = n.y, a10 = n.z, a11 = n.w;
        const float b0 = a0 + a1, b1 = a2 + a3, b2 = a4 + a5;
        const float b3 = a6 + a7, b4 = a8 + a9, b5 = a10 + a11;
        const float c0 = b0 + b1;   // a0..a3
        const float c1 = b2 + b3;   // a4..a7
        const float c2 = b4 + b5;   // a8..a11
        float4 h;
        h.x = (c0 + c1) + a8;       // a0..a8
        h.w = (c1 + c2) + a3;       // a3..a11
        h.y = (h.x - a0) + a9;      // a1..a9
        h.z = (h.w - a11) + a2;     // a2..a10
        return h;
    };

    // ---- vertical running sum over 9-row register ring ----
    float4 ring[RING];
    float4 vsum = f4zero();

    // Prologue: ring[k] = h(row0-4+k), k=0..7
#pragma unroll
    for (int k = 0; k < 2 * RR; ++k) {
        const int ir = row0 - RR + k;
        ring[k] = hsum(ir, vload(ir));
        vsum = add4(vsum, ring[k]);
    }

    float4 vnext = vload(row0 + RR);   // center of row i+4, one row ahead

    int i = row0;
#pragma unroll 1
    for (int g = 0; g < STRIP / RING; ++g) {
#pragma unroll
        for (int u = 0; u < RING; ++u) {
            float4 vcur = vnext;
            vnext = vload(i + RR + 1);              // keep next center in flight

            float4 h = hsum(i + RR, vcur);          // h(i+4)
            float4 old = ring[u];                   // h(i-4)
            ring[(u + 2 * RR) % RING] = h;          // compile-time slot

            vsum = add4(vsum, h);
            __stcs(reinterpret_cast<float4*>(obase + (size_t)i * WD + col), vsum);
            vsum = sub4(vsum, old);
            ++i;
        }
    }
}

extern "C" void kernel_launch(void* const* d_in, const int* in_sizes, int n_in,
                              void* d_out, int out_size) {
    const float* x = (const float*)d_in[0];
    // d_in[1] is r (int32, fixed at 4) — hardcoded.
    float* out = (float*)d_out;
    boxfilter9x9_kernel<<<NBLOCKS, THREADS>>>(x, out);
}

// round 10
// speedup vs baseline: 1.1051x; 1.1039x over previous
#include <cuda_runtime.h>

// BoxFilter 9x9 zero-padded window sum. Fixed shape (8,3,1080,1920) fp32, r=4.
//
// v6: MLP=4. Rows processed in groups of 4; all 4 next-group center loads are
// issued as a front-batch before computing the current group, so each warp
// keeps 4 independent LDG.128 in flight (was 1 -> DRAM stuck at ~55%).
// Ring buffer in SMEM (warp-private), R3 geometry (450 x 256, single wave).

#define RR 4
#define WD 1920
#define HD 1080
#define NIMG 24                  // B*C
#define TILE_W 128               // 32 lanes x float4
#define NTX (WD / TILE_W)        // 15
#define STRIP 108                // output rows per warp; 27 groups of 4
#define NSTR (HD / STRIP)        // 10
#define WPB 8
#define THREADS (WPB * 32)       // 256
#define NBLOCKS (NIMG * NTX * NSTR / WPB)   // 450
#define RING 9
#define GRP 4

__device__ __forceinline__ float4 f4zero() { return make_float4(0.f, 0.f, 0.f, 0.f); }
__device__ __forceinline__ float4 add4(float4 a, float4 b) {
    return make_float4(a.x + b.x, a.y + b.y, a.z + b.z, a.w + b.w);
}
__device__ __forceinline__ float4 sub4(float4 a, float4 b) {
    return make_float4(a.x - b.x, a.y - b.y, a.z - b.z, a.w - b.w);
}

__global__ __launch_bounds__(THREADS, 4)
void boxfilter9x9_kernel(const float* __restrict__ x, float* __restrict__ out) {
    __shared__ float4 ring_sm[WPB][RING][32];

    const int warp = threadIdx.x >> 5;
    const int lane = threadIdx.x & 31;
    const int gwarp = blockIdx.x * WPB + warp;

    const int strip = gwarp % NSTR;
    const int t     = gwarp / NSTR;
    const int tx    = t % NTX;
    const int img   = t / NTX;

    const float* __restrict__ base  = x   + (size_t)img * HD * WD;
    float* __restrict__       obase = out + (size_t)img * HD * WD;

    const int col  = tx * TILE_W + lane * 4;
    const int row0 = strip * STRIP;

    const bool has_l = (col >= 4);         // p covers col-4..col-1
    const bool has_r = (col <= WD - 8);    // n covers col+4..col+7

    float4* const myring = &ring_sm[warp][0][lane];   // slot stride = 32 float4

    // Center load for one row (1 LDG.128).
    auto vload = [&](int ir) -> float4 {
        if ((unsigned)ir >= (unsigned)HD) return f4zero();
        return *reinterpret_cast<const float4*>(base + (size_t)ir * WD + col);
    };

    // Horizontal 9-tap sums; p/n are reuse hits (neighbor-lane v lines).
    auto hsum = [&](int ir, float4 v) -> float4 {
        float4 p = f4zero(), n = f4zero();
        if ((unsigned)ir < (unsigned)HD) {
            const float* rp = base + (size_t)ir * WD;
            if (has_l) p = *reinterpret_cast<const float4*>(rp + col - 4);
            if (has_r) n = *reinterpret_cast<const float4*>(rp + col + 4);
        }
        const float a0 = p.x, a1 = p.y, a2 = p.z, a3 = p.w;
        const float a4 = v.x, a5 = v.y, a6 = v.z, a7 = v.w;
        const float a8 = n.x, a9 = n.y, a10 = n.z, a11 = n.w;
        const float b0 = a0 + a1, b1 = a2 + a3, b2 = a4 + a5;
        const float b3 = a6 + a7, b4 = a8 + a9, b5 = a10 + a11;
        const float c0 = b0 + b1, c1 = b2 + b3, c2 = b4 + b5;
        float4 h;
        h.x = (c0 + c1) + a8;       // a0..a8
        h.w = (c1 + c2) + a3;       // a3..a11
        h.y = (h.x - a0) + a9;      // a1..a9
        h.z = (h.w - a11) + a2;     // a2..a10
        return h;
    };

    // ---- prologue: ring slots 0..7 = h(row0-4 .. row0+3), batched loads ----
    float4 vsum = f4zero();
    {
        float4 pv[4];
#pragma unroll
        for (int k = 0; k < 4; ++k) pv[k] = vload(row0 - RR + k);
#pragma unroll
        for (int k = 0; k < 4; ++k) {
            float4 h = hsum(row0 - RR + k, pv[k]);
            myring[k * 32] = h;
            vsum = add4(vsum, h);
        }
#pragma unroll
        for (int k = 0; k < 4; ++k) pv[k] = vload(row0 + k);
#pragma unroll
        for (int k = 0; k < 4; ++k) {
            float4 h = hsum(row0 + k, pv[k]);
            myring[(4 + k) * 32] = h;
            vsum = add4(vsum, h);
        }
    }

    // ---- main loop: group-of-4 rows, 4 center loads in flight ----
    float4 q[GRP];
#pragma unroll
    for (int k = 0; k < GRP; ++k) q[k] = vload(row0 + RR + k);

    int s_new = 8;   // slot for h(i+4)
    int s_old = 0;   // slot of h(i-4)
    int i = row0;

#pragma unroll 1
    for (int g = 0; g < STRIP / GRP; ++g) {
        // Front-batch next group's 4 center loads (independent, MLP=4).
        float4 qn[GRP];
#pragma unroll
        for (int k = 0; k < GRP; ++k) qn[k] = vload(i + RR + GRP + k);

        // Compute/store current group's 4 rows.
#pragma unroll
        for (int u = 0; u < GRP; ++u) {
            float4 h   = hsum(i + RR, q[u]);     // h(i+4)
            float4 old = myring[s_old * 32];     // h(i-4), 9 rows stale (warp-private)
            myring[s_new * 32] = h;

            vsum = add4(vsum, h);
            __stcs(reinterpret_cast<float4*>(obase + (size_t)i * WD + col), vsum);
            vsum = sub4(vsum, old);

            s_new = (s_new + 1 == RING) ? 0 : s_new + 1;
            s_old = (s_old + 1 == RING) ? 0 : s_old + 1;
            ++i;
        }

#pragma unroll
        for (int k = 0; k < GRP; ++k) q[k] = qn[k];
    }
}

extern "C" void kernel_launch(void* const* d_in, const int* in_sizes, int n_in,
                              void* d_out, int out_size) {
    const float* x = (const float*)d_in[0];
    // d_in[1] is r (int32, fixed at 4) — hardcoded.
    float* out = (float*)d_out;
    boxfilter9x9_kernel<<<NBLOCKS, THREADS>>>(x, out);
}

// round 12
// speedup vs baseline: 1.1582x; 1.0481x over previous
#include <cuda_runtime.h>
#include <cstdint>

// BoxFilter 9x9 zero-padded window sum. Fixed shape (8,3,1080,1920) fp32, r=4.
//
// v8 == v7 resubmit (previous round died to a broker/container infra error,
// not a kernel failure).
//
// Design: cp.async producer pipeline. Each warp streams its 136-col input
// rows (center + both halos) into a DEPTH=6 smem stage ring via cp.async.cg
// (fire-and-forget -> loads stay outstanding continuously; v6's register
// batches had ~12% DRAM duty cycle). Consume = 3 conflict-free LDS.128
// (p/v/n) + h-tree + vertical 9-row running sum (smem ring).

#define RR 4
#define WD 1920
#define HD 1080
#define NIMG 24                  // B*C
#define TILE_W 128               // 32 lanes x float4
#define NTX 15                   // 1920/128
#define STRIP 108
#define NSTR 10                  // 1080/108
#define WPB 4
#define THREADS 128
#define NBLOCKS 900              // 24*15*10 warps / 4
#define RING 9
#define DEPTH 6                  // smem pipeline stages (input rows in flight)
#define CHUNKS 34                // 136 floats = 34 x 16B per stage row
#define NROWS (STRIP + 2 * RR)   // 116 input rows per strip

__device__ __forceinline__ float4 f4zero() { return make_float4(0.f, 0.f, 0.f, 0.f); }
__device__ __forceinline__ float4 add4(float4 a, float4 b) {
    return make_float4(a.x + b.x, a.y + b.y, a.z + b.z, a.w + b.w);
}
__device__ __forceinline__ float4 sub4(float4 a, float4 b) {
    return make_float4(a.x - b.x, a.y - b.y, a.z - b.z, a.w - b.w);
}

__global__ __launch_bounds__(THREADS, 6)
void boxfilter9x9_kernel(const float* __restrict__ x, float* __restrict__ out) {
    __shared__ float4 stage_sm[WPB][DEPTH][CHUNKS];   // 13,056 B
    __shared__ float4 ring_sm[WPB][RING][32];         // 18,432 B

    const int warp = threadIdx.x >> 5;
    const int lane = threadIdx.x & 31;
    const int gwarp = blockIdx.x * WPB + warp;

    const int strip = gwarp % NSTR;
    const int t     = gwarp / NSTR;
    const int tx    = t % NTX;
    const int img   = t / NTX;

    const float* __restrict__ base  = x   + (size_t)img * HD * WD;
    float* __restrict__       obase = out + (size_t)img * HD * WD;

    const int col0 = tx * TILE_W;
    const int row0 = strip * STRIP;

    // Zero all stages once: OOB halo chunks (left edge chunk0 / right edge
    // chunk33) are never refilled afterwards and must read as zero.
    for (int i = threadIdx.x; i < WPB * DEPTH * CHUNKS; i += THREADS)
        reinterpret_cast<float4*>(stage_sm)[i] = f4zero();
    __syncthreads();

    const bool skip_c0  = (tx == 0);        // chunk 0 would read cols -4..-1
    const bool skip_c33 = (tx == NTX - 1);  // chunk 33 would read cols 1920..1923

    float4 (* const mystage)[CHUNKS] = stage_sm[warp];
    float4* const myring = &ring_sm[warp][0][lane];   // slot stride = 32 float4

    // Stream input row ir into stage slot. Chunk c covers cols col0-4+4c.
    // Lane k -> chunk k; lanes 0,1 also chunks 32,33. Always commits a group
    // (empty groups complete immediately; keeps wait_group counts uniform).
    auto refill = [&](int ir, int slot) {
        if ((unsigned)ir < (unsigned)HD) {
            const float* rp = base + (size_t)ir * WD + (col0 - 4);  // 16B-aligned
            if (!(skip_c0 && lane == 0)) {
                unsigned d = (unsigned)__cvta_generic_to_shared(&mystage[slot][lane]);
                asm volatile("cp.async.cg.shared.global [%0], [%1], 16;"
                             :: "r"(d), "l"(rp + lane * 4));
            }
            if (lane < 2 && !(skip_c33 && lane == 1)) {
                unsigned d = (unsigned)__cvta_generic_to_shared(&mystage[slot][32 + lane]);
                asm volatile("cp.async.cg.shared.global [%0], [%1], 16;"
                             :: "r"(d), "l"(rp + (32 + lane) * 4));
            }
        } else {
            mystage[slot][lane] = f4zero();
            if (lane < 2) mystage[slot][32 + lane] = f4zero();
        }
        asm volatile("cp.async.commit_group;");
    };

    auto hsum = [&](float4 p, float4 v, float4 n) -> float4 {
        const float a0 = p.x, a1 = p.y, a2 = p.z, a3 = p.w;
        const float a4 = v.x, a5 = v.y, a6 = v.z, a7 = v.w;
        const float a8 = n.x, a9 = n.y, a10 = n.z, a11 = n.w;
        const float b0 = a0 + a1, b1 = a2 + a3, b2 = a4 + a5;
        const float b3 = a6 + a7, b4 = a8 + a9, b5 = a10 + a11;
        const float c0 = b0 + b1, c1 = b2 + b3, c2 = b4 + b5;
        float4 h;
        h.x = (c0 + c1) + a8;       // a0..a8
        h.w = (c1 + c2) + a3;       // a3..a11
        h.y = (h.x - a0) + a9;      // a1..a9
        h.z = (h.w - a11) + a2;     // a2..a10
        return h;
    };

    // ---- prologue A: fill pipeline with input rows 0..DEPTH-1 ----
#pragma unroll
    for (int k = 0; k < DEPTH; ++k) refill(row0 - RR + k, k);

    // ---- prologue B: consume input rows 0..7 -> ring[0..7] ----
    float4 vsum = f4zero();
    int ss = 0;                       // stage slot of next row to consume
#pragma unroll
    for (int k = 0; k < 2 * RR; ++k) {
        asm volatile("cp.async.wait_group %0;" :: "n"(DEPTH - 1));
        __syncwarp();
        float4 p = mystage[ss][lane];
        float4 v = mystage[ss][lane + 1];
        float4 n = mystage[ss][lane + 2];
        float4 h = hsum(p, v, n);
        myring[k * 32] = h;
        vsum = add4(vsum, h);
        refill(row0 - RR + k + DEPTH, ss);
        ss = (ss + 1 == DEPTH) ? 0 : ss + 1;
    }

    // ---- main loop: one output row per consumed input row ----
    int s_old = 0, s_new = 8;
    int i = row0;
#pragma unroll 2
    for (int k = 2 * RR; k < NROWS; ++k) {
        asm volatile("cp.async.wait_group %0;" :: "n"(DEPTH - 1));
        __syncwarp();
        float4 p = mystage[ss][lane];
        float4 v = mystage[ss][lane + 1];
        float4 n = mystage[ss][lane + 2];
        float4 h = hsum(p, v, n);          // h(i+4)

        float4 old = myring[s_old * 32];   // h(i-4)
        myring[s_new * 32] = h;

        vsum = add4(vsum, h);
        __stcs(reinterpret_cast<float4*>(obase + (size_t)i * WD + col0 + lane * 4), vsum);
        vsum = sub4(vsum, old);

        if (k + DEPTH < NROWS) refill(row0 - RR + k + DEPTH, ss);
        else asm volatile("cp.async.commit_group;");   // keep group count uniform

        ss = (ss + 1 == DEPTH) ? 0 : ss + 1;
        s_old = (s_old + 1 == RING) ? 0 : s_old + 1;
        s_new = (s_new + 1 == RING) ? 0 : s_new + 1;
        ++i;
    }
    asm volatile("cp.async.wait_group 0;");
}

extern "C" void kernel_launch(void* const* d_in, const int* in_sizes, int n_in,
                              void* d_out, int out_size) {
    const float* x = (const float*)d_in[0];
    // d_in[1] is r (int32, fixed at 4) — hardcoded.
    float* out = (float*)d_out;
    boxfilter9x9_kernel<<<NBLOCKS, THREADS>>>(x, out);
}